// round 9
// baseline (speedup 1.0000x reference)
#include <cuda_runtime.h>
#include <cuda_fp16.h>

// ---------------- problem constants (dataset-fixed) ----------------
#define F_IN 128
#define HDIM 64
#define NEG_SLOPE 0.2f

constexpr int MAXN = 100000;
constexpr int MAXE_TOT = 1700000;   // E (1.6M) + N self loops (100k)

// ---------------- device scratch ----------------
__device__ __half2 g_h1h[(size_t)MAXN * (HDIM / 2)];   // 12.8 MB, fp16 features
__device__ float g_as1[MAXN];
__device__ float g_ad1[MAXN];
__device__ float4 g_pack2[MAXN];          // {h2.x, h2.y, as2, ad2}

__device__ int g_cnt[MAXN];               // zero-init; re-zeroed by scan_k each replay
__device__ int g_rowptr[MAXN + 1];
__device__ int g_cursor[MAXN];
__device__ int g_colsrc[MAXE_TOT];
__device__ int g_bsum[64];                // block totals; 0 = pending (zf_k zeroes)

// ---------------- f32x2 helpers (Blackwell packed fp32) ----------------
__device__ __forceinline__ unsigned long long f32x2_fma(
    unsigned long long a, unsigned long long b, unsigned long long c) {
    unsigned long long d;
    asm("fma.rn.f32x2 %0, %1, %2, %3;" : "=l"(d) : "l"(a), "l"(b), "l"(c));
    return d;
}
__device__ __forceinline__ unsigned long long f32x2_bcast(float x) {
    unsigned long long d;
    unsigned int u = __float_as_uint(x);
    asm("mov.b64 %0, {%1, %1};" : "=l"(d) : "r"(u));
    return d;
}
__device__ __forceinline__ unsigned int h2_as_u32(__half2 h) {
    union { __half2 h; unsigned int u; } cvt;
    cvt.h = h;
    return cvt.u;
}

// ---------------- zf: reset lookback slots (launch #1) ----------------
__global__ void zf_k() {
    if (threadIdx.x < 64) g_bsum[threadIdx.x] = 0;
}

// ---------------- CSR build (edges are int32: proven R1/R4) ----------------
__global__ void hist_k(const int* __restrict__ ei, int E, int N) {
    int e = blockIdx.x * blockDim.x + threadIdx.x;
    if (e >= E) return;
    int d = ei[E + e];
    if (d >= 0 && d < N) atomicAdd(&g_cnt[d], 1);
}

// single-pass scan with all-predecessor poll (nb <= 64 blocks, all resident).
// Publishes block totals (always > 0) to g_bsum; 0 means pending.
__global__ __launch_bounds__(256) void scan_k(int N, int nb) {
    int tid = threadIdx.x, lane = tid & 31, warp = tid >> 5;
    int bid = blockIdx.x;
    int base = bid * 2048 + tid * 8;

    int v[8];
    int ts = 0;
#pragma unroll
    for (int j = 0; j < 8; j++) {
        int i = base + j;
        v[j] = (i < N) ? (g_cnt[i] + 1) : 0;   // +1 self loop
        ts += v[j];
    }
    int incl = ts;
#pragma unroll
    for (int o = 1; o < 32; o <<= 1) {
        int t = __shfl_up_sync(0xffffffffu, incl, o);
        if (lane >= o) incl += t;
    }
    int texcl = incl - ts;

    __shared__ int ws[8], s_tot, s_pre[2];
    if (lane == 31) ws[warp] = incl;
    __syncthreads();
    if (tid == 0) {
        int run = 0;
#pragma unroll
        for (int w = 0; w < 8; w++) { int t = ws[w]; ws[w] = run; run += t; }
        s_tot = run;
        *(volatile int*)&g_bsum[bid] = run;    // publish (run >= 1696 > 0)
    }
    __syncthreads();

    // poll all predecessors, sum their totals
    int acc = 0;
    if (tid < 64) {
        if (tid < bid) {
            volatile int* vb = (volatile int*)g_bsum;
            int t;
            do { t = vb[tid]; } while (t == 0);
            acc = t;
        }
#pragma unroll
        for (int o = 16; o; o >>= 1) acc += __shfl_xor_sync(0xffffffffu, acc, o);
        if (lane == 0) s_pre[tid >> 5] = acc;
    }
    __syncthreads();
    int pre = s_pre[0] + s_pre[1];
    if (bid == nb - 1 && tid == 0) g_rowptr[N] = pre + s_tot;

    int run = pre + ws[warp] + texcl;
#pragma unroll
    for (int j = 0; j < 8; j++) {
        int i = base + j;
        if (i < N) {
            g_rowptr[i] = run; g_cursor[i] = run; run += v[j];
            g_cnt[i] = 0;   // reset for next replay
        }
    }
}

__global__ void scatter_k(const int* __restrict__ ei, int E, int N) {
    int e = blockIdx.x * blockDim.x + threadIdx.x;
    if (e >= E + N) return;
    int s, d;
    if (e < E) {
        s = ei[e];
        d = ei[E + e];
        if (s < 0 || s >= N || d < 0 || d >= N) return;
    } else {
        s = d = e - E;   // self loop
    }
    int pos = atomicAdd(&g_cursor[d], 1);
    if (pos >= 0 && pos < MAXE_TOT) g_colsrc[pos] = s;
}

// ---------------- layer 1 GEMM: f32x2, 4 rows x 8 cols per thread ----------------
// 256 threads: cg = tid&7 (8 col-groups x 8 cols), rg = tid>>3 (32 row-groups x 4 rows)
// => 128 rows/block. Per k-step/thread: 16 FFMA2 + 4 dup-mov + ~2.75 LDS = 0.72 slot/MAC.
// smem: Wsh [128][64] f32 (32KB) + xs [128 rows][132 pad] f32 (67.6KB) = 98KB.
#define G1ROWS 128
#define XPAD 132
__global__ __launch_bounds__(256) void gemm1_k(
    const float* __restrict__ x, const float* __restrict__ W1,
    const float* __restrict__ a_src1, const float* __restrict__ a_dst1, int N) {
    extern __shared__ float smem[];
    float* Wsh = smem;                   // 8192 floats
    float* xs  = smem + F_IN * HDIM;     // 128*132 floats
    int tid = threadIdx.x;
    int row0 = blockIdx.x * G1ROWS;
    if (row0 >= N) return;

    const float4* W4 = (const float4*)W1;
    float4* Wsh4 = (float4*)Wsh;
#pragma unroll
    for (int i = tid; i < F_IN * HDIM / 4; i += 256) Wsh4[i] = W4[i];

    int nrows = N - row0; if (nrows > G1ROWS) nrows = G1ROWS;
    const float4* x4 = (const float4*)(x + (size_t)row0 * F_IN);
    for (int i = tid; i < nrows * (F_IN / 4); i += 256) {
        int row = i >> 5, f4 = i & 31;
        *(float4*)&xs[row * XPAD + f4 * 4] = x4[i];
    }
    __syncthreads();

    int cg = tid & 7, rg = tid >> 3;
    int rbase = rg * 4;
    const unsigned long long* W8 = (const unsigned long long*)Wsh;

    unsigned long long acc[4][4];   // [row][colpair]
#pragma unroll
    for (int r = 0; r < 4; r++)
#pragma unroll
        for (int p = 0; p < 4; p++) acc[r][p] = 0ull;

    for (int k0 = 0; k0 < F_IN; k0 += 4) {
        float4 xv[4];
#pragma unroll
        for (int r = 0; r < 4; r++)
            xv[r] = *(const float4*)&xs[(rbase + r) * XPAD + k0];
#pragma unroll
        for (int kk = 0; kk < 4; kk++) {
            const unsigned long long* wrow = &W8[(k0 + kk) * 32 + 4 * cg];
            ulonglong2 wa = *(const ulonglong2*)(wrow);
            ulonglong2 wb = *(const ulonglong2*)(wrow + 2);
#pragma unroll
            for (int r = 0; r < 4; r++) {
                float xk = (kk == 0) ? xv[r].x : (kk == 1) ? xv[r].y
                          : (kk == 2) ? xv[r].z : xv[r].w;
                unsigned long long xd = f32x2_bcast(xk);
                acc[r][0] = f32x2_fma(xd, wa.x, acc[r][0]);
                acc[r][1] = f32x2_fma(xd, wa.y, acc[r][1]);
                acc[r][2] = f32x2_fma(xd, wb.x, acc[r][2]);
                acc[r][3] = f32x2_fma(xd, wb.y, acc[r][3]);
            }
        }
    }

    // epilogue: h1 (fp16) + alpha projections (8-lane group reduce, no divergence)
    float4 as_a = *(const float4*)&a_src1[8 * cg];
    float4 as_b = *(const float4*)&a_src1[8 * cg + 4];
    float4 ad_a = *(const float4*)&a_dst1[8 * cg];
    float4 ad_b = *(const float4*)&a_dst1[8 * cg + 4];
#pragma unroll
    for (int r = 0; r < 4; r++) {
        float h[8];
#pragma unroll
        for (int p = 0; p < 4; p++) {
            h[2 * p]     = __uint_as_float((unsigned int)acc[r][p]);
            h[2 * p + 1] = __uint_as_float((unsigned int)(acc[r][p] >> 32));
        }
        float aps = h[0] * as_a.x + h[1] * as_a.y + h[2] * as_a.z + h[3] * as_a.w
                  + h[4] * as_b.x + h[5] * as_b.y + h[6] * as_b.z + h[7] * as_b.w;
        float apd = h[0] * ad_a.x + h[1] * ad_a.y + h[2] * ad_a.z + h[3] * ad_a.w
                  + h[4] * ad_b.x + h[5] * ad_b.y + h[6] * ad_b.z + h[7] * ad_b.w;
#pragma unroll
        for (int o = 1; o < 8; o <<= 1) {
            aps += __shfl_xor_sync(0xffffffffu, aps, o);
            apd += __shfl_xor_sync(0xffffffffu, apd, o);
        }
        int lr = rbase + r;
        if (lr < nrows) {
            int row = row0 + lr;
            uint4 st;
            st.x = h2_as_u32(__floats2half2_rn(h[0], h[1]));
            st.y = h2_as_u32(__floats2half2_rn(h[2], h[3]));
            st.z = h2_as_u32(__floats2half2_rn(h[4], h[5]));
            st.w = h2_as_u32(__floats2half2_rn(h[6], h[7]));
            *(uint4*)&g_h1h[(size_t)row * 32 + 4 * cg] = st;
            if (cg == 0) { g_as1[row] = aps; g_ad1[row] = apd; }
        }
    }
}

// ---------------- layer 1 aggregation + relu + layer 2 GEMM + alpha2 ----------------
__global__ __launch_bounds__(256) void agg1_k(
    const float* __restrict__ b1, const float* __restrict__ W2,
    const float* __restrict__ a_src2, const float* __restrict__ a_dst2, int N) {
    int gw = (int)((blockIdx.x * blockDim.x + threadIdx.x) >> 5);
    int lane = threadIdx.x & 31;
    if (gw >= N) return;
    int d = gw;
    int beg = g_rowptr[d], end = g_rowptr[d + 1];
    float ad = g_ad1[d];
    float accx = 0.f, accy = 0.f, denl = 0.f;
    for (int base = beg; base < end; base += 32) {
        int m = end - base; if (m > 32) m = 32;
        int s_l = 0; float p_l = 0.f;
        if (lane < m) {
            s_l = g_colsrc[base + lane];
            float ev = g_as1[s_l] + ad;
            ev = ev > 0.f ? ev : NEG_SLOPE * ev;
            p_l = __expf(ev);
        }
        denl += p_l;
#pragma unroll 8
        for (int j = 0; j < m; j++) {
            int s  = __shfl_sync(0xffffffffu, s_l, j);
            float p = __shfl_sync(0xffffffffu, p_l, j);
            __half2 hv = g_h1h[(size_t)s * 32 + lane];
            float2 f = __half22float2(hv);
            accx = fmaf(p, f.x, accx);
            accy = fmaf(p, f.y, accy);
        }
    }
    float den = denl;
#pragma unroll
    for (int o = 16; o; o >>= 1) den += __shfl_xor_sync(0xffffffffu, den, o);
    float inv = 1.0f / (den + 1e-16f);
    float2 bv = ((const float2*)b1)[lane];
    float h0 = accx * inv + bv.x; h0 = h0 > 0.f ? h0 : 0.f;
    float h1 = accy * inv + bv.y; h1 = h1 > 0.f ? h1 : 0.f;
    float4 w4 = ((const float4*)W2)[lane];
    float c0 = h0 * w4.x + h1 * w4.z;
    float c1 = h0 * w4.y + h1 * w4.w;
#pragma unroll
    for (int o = 16; o; o >>= 1) {
        c0 += __shfl_xor_sync(0xffffffffu, c0, o);
        c1 += __shfl_xor_sync(0xffffffffu, c1, o);
    }
    if (lane == 0) {
        g_pack2[d] = make_float4(c0, c1,
                                 c0 * a_src2[0] + c1 * a_src2[1],
                                 c0 * a_dst2[0] + c1 * a_dst2[1]);
    }
}

// ---------------- layer 2 aggregation ----------------
__global__ __launch_bounds__(256) void agg2_k(const float* __restrict__ b2,
                                              float* __restrict__ out, int N) {
    int gw = (int)((blockIdx.x * blockDim.x + threadIdx.x) >> 5);
    int lane = threadIdx.x & 31;
    if (gw >= N) return;
    int d = gw;
    int beg = g_rowptr[d], end = g_rowptr[d + 1];
    float ad = g_pack2[d].w;
    float a0 = 0.f, a1 = 0.f, den = 0.f;
    for (int e = beg + lane; e < end; e += 32) {
        int s = g_colsrc[e];
        float4 pv = g_pack2[s];
        float ev = pv.z + ad;
        ev = ev > 0.f ? ev : NEG_SLOPE * ev;
        float p = __expf(ev);
        a0 = fmaf(p, pv.x, a0);
        a1 = fmaf(p, pv.y, a1);
        den += p;
    }
#pragma unroll
    for (int o = 16; o; o >>= 1) {
        a0 += __shfl_xor_sync(0xffffffffu, a0, o);
        a1 += __shfl_xor_sync(0xffffffffu, a1, o);
        den += __shfl_xor_sync(0xffffffffu, den, o);
    }
    if (lane == 0) {
        float inv = 1.0f / (den + 1e-16f);
        ((float2*)out)[d] = make_float2(a0 * inv + b2[0], a1 * inv + b2[1]);
    }
}

// ---------------- launch ----------------
extern "C" void kernel_launch(void* const* d_in, const int* in_sizes, int n_in,
                              void* d_out, int out_size) {
    const float* x        = (const float*)d_in[0];
    const int*   ei       = (const int*)d_in[1];   // int32 (proven R1 trap / R4 probe)
    const float* W1       = (const float*)d_in[2];
    const float* a_src1   = (const float*)d_in[3];
    const float* a_dst1   = (const float*)d_in[4];
    const float* b1       = (const float*)d_in[5];
    const float* W2       = (const float*)d_in[6];
    const float* a_src2   = (const float*)d_in[7];
    const float* a_dst2   = (const float*)d_in[8];
    const float* b2       = (const float*)d_in[9];

    int N = in_sizes[0] / F_IN;
    int E = in_sizes[1] / 2;

    size_t g1smem = (F_IN * HDIM + G1ROWS * XPAD) * sizeof(float);  // 98KB

    static int inited = 0;
    static int have_stream = 0;
    static cudaStream_t s2;
    static cudaEvent_t evFork, evJoin;
    if (!inited) {
        cudaFuncSetAttribute(gemm1_k, cudaFuncAttributeMaxDynamicSharedMemorySize,
                             (int)g1smem);
        if (cudaStreamCreateWithFlags(&s2, cudaStreamNonBlocking) == cudaSuccess &&
            cudaEventCreateWithFlags(&evFork, cudaEventDisableTiming) == cudaSuccess &&
            cudaEventCreateWithFlags(&evJoin, cudaEventDisableTiming) == cudaSuccess) {
            have_stream = 1;
        }
        inited = 1;
    }

    int g1grid = (N + G1ROWS - 1) / G1ROWS;
    int nb = (N + 2047) / 2048;   // 49 for N=100k (<= 64)

    if (have_stream) { cudaEventRecord(evFork, 0); cudaStreamWaitEvent(s2, evFork, 0); }

    // API launch order fixed so ncu (-s 5 -c 1) captures #6 = agg1_k.
    zf_k<<<1, 64>>>();                                          // #1
    hist_k<<<(E + 255) / 256, 256>>>(ei, E, N);                 // #2
    scan_k<<<nb, 256>>>(N, nb);                                 // #3
    scatter_k<<<(E + N + 255) / 256, 256>>>(ei, E, N);          // #4
    if (have_stream) {
        gemm1_k<<<g1grid, 256, g1smem, s2>>>(x, W1, a_src1, a_dst1, N);  // #5
        cudaEventRecord(evJoin, s2);
        cudaStreamWaitEvent(0, evJoin, 0);
    } else {
        gemm1_k<<<g1grid, 256, g1smem>>>(x, W1, a_src1, a_dst1, N);
    }
    agg1_k<<<(N + 7) / 8, 256>>>(b1, W2, a_src2, a_dst2, N);    // #6  <- ncu capture
    agg2_k<<<(N + 7) / 8, 256>>>(b2, (float*)d_out, N);         // #7
}

// round 10
// speedup vs baseline: 1.0972x; 1.0972x over previous
#include <cuda_runtime.h>
#include <cuda_fp16.h>

// ---------------- problem constants (dataset-fixed) ----------------
#define F_IN 128
#define HDIM 64
#define NEG_SLOPE 0.2f

constexpr int MAXN = 100000;
constexpr int MAXE_TOT = 1700000;   // E (1.6M) + N self loops (100k)

// ---------------- device scratch ----------------
__device__ __half2 g_h1h[(size_t)MAXN * (HDIM / 2)];   // 12.8 MB, fp16 features
__device__ float g_as1[MAXN];
__device__ float g_ad1[MAXN];
__device__ float4 g_pack2[MAXN];          // {h2.x, h2.y, as2, ad2}

__device__ int g_cnt[MAXN];               // zero-init; re-zeroed by scan_k each replay
__device__ int g_rowptr[MAXN + 1];
__device__ int g_cursor[MAXN];
__device__ int g_colsrc[MAXE_TOT];
__device__ int g_bsum[64];                // block totals; 0 = pending (hist blk0 zeroes)

// ---------------- f32x2 helpers (Blackwell packed fp32) ----------------
__device__ __forceinline__ unsigned long long f32x2_fma(
    unsigned long long a, unsigned long long b, unsigned long long c) {
    unsigned long long d;
    asm("fma.rn.f32x2 %0, %1, %2, %3;" : "=l"(d) : "l"(a), "l"(b), "l"(c));
    return d;
}
__device__ __forceinline__ unsigned long long f32x2_bcast(float x) {
    unsigned long long d;
    unsigned int u = __float_as_uint(x);
    asm("mov.b64 %0, {%1, %1};" : "=l"(d) : "r"(u));
    return d;
}
__device__ __forceinline__ unsigned int h2_as_u32(__half2 h) {
    union { __half2 h; unsigned int u; } cvt;
    cvt.h = h;
    return cvt.u;
}

// ---------------- CSR build (edges are int32: proven R1/R4) ----------------
// block 0 also resets the scan lookback slots (read only by scan_k, which is
// stream-ordered after hist_k).
__global__ void hist_k(const int* __restrict__ ei, int E, int N) {
    if (blockIdx.x == 0 && threadIdx.x < 64) g_bsum[threadIdx.x] = 0;
    int e = blockIdx.x * blockDim.x + threadIdx.x;
    if (e >= E) return;
    int d = ei[E + e];
    if (d >= 0 && d < N) atomicAdd(&g_cnt[d], 1);
}

// single-pass scan with all-predecessor poll (nb <= 64 blocks, all resident).
// Publishes block totals (always > 0) to g_bsum; 0 means pending.
__global__ __launch_bounds__(256) void scan_k(int N, int nb) {
    int tid = threadIdx.x, lane = tid & 31, warp = tid >> 5;
    int bid = blockIdx.x;
    int base = bid * 2048 + tid * 8;

    int v[8];
    int ts = 0;
#pragma unroll
    for (int j = 0; j < 8; j++) {
        int i = base + j;
        v[j] = (i < N) ? (g_cnt[i] + 1) : 0;   // +1 self loop
        ts += v[j];
    }
    int incl = ts;
#pragma unroll
    for (int o = 1; o < 32; o <<= 1) {
        int t = __shfl_up_sync(0xffffffffu, incl, o);
        if (lane >= o) incl += t;
    }
    int texcl = incl - ts;

    __shared__ int ws[8], s_tot, s_pre[2];
    if (lane == 31) ws[warp] = incl;
    __syncthreads();
    if (tid == 0) {
        int run = 0;
#pragma unroll
        for (int w = 0; w < 8; w++) { int t = ws[w]; ws[w] = run; run += t; }
        s_tot = run;
        *(volatile int*)&g_bsum[bid] = run;    // publish (run >= 1696 > 0)
    }
    __syncthreads();

    // poll all predecessors, sum their totals
    int acc = 0;
    if (tid < 64) {
        if (tid < bid) {
            volatile int* vb = (volatile int*)g_bsum;
            int t;
            do { t = vb[tid]; } while (t == 0);
            acc = t;
        }
#pragma unroll
        for (int o = 16; o; o >>= 1) acc += __shfl_xor_sync(0xffffffffu, acc, o);
        if (lane == 0) s_pre[tid >> 5] = acc;
    }
    __syncthreads();
    int pre = s_pre[0] + s_pre[1];
    if (bid == nb - 1 && tid == 0) g_rowptr[N] = pre + s_tot;

    int run = pre + ws[warp] + texcl;
#pragma unroll
    for (int j = 0; j < 8; j++) {
        int i = base + j;
        if (i < N) {
            g_rowptr[i] = run; g_cursor[i] = run; run += v[j];
            g_cnt[i] = 0;   // reset for next replay
        }
    }
}

__global__ void scatter_k(const int* __restrict__ ei, int E, int N) {
    int e = blockIdx.x * blockDim.x + threadIdx.x;
    if (e >= E + N) return;
    int s, d;
    if (e < E) {
        s = ei[e];
        d = ei[E + e];
        if (s < 0 || s >= N || d < 0 || d >= N) return;
    } else {
        s = d = e - E;   // self loop
    }
    int pos = atomicAdd(&g_cursor[d], 1);
    if (pos >= 0 && pos < MAXE_TOT) g_colsrc[pos] = s;
}

// ---------------- layer 1 GEMM via packed fma.f32x2 (R5 tile: PROVEN) ----------------
// 256 threads: lane = colpair (64 cols = 32 pairs), warp (8) owns 8 rows.
// 64 rows/block. Dynamic smem: Wsh [128][64] 32KB + xs [64][128] 32KB.
#define G1ROWS 64
__global__ __launch_bounds__(256) void gemm1_k(
    const float* __restrict__ x, const float* __restrict__ W1,
    const float* __restrict__ a_src1, const float* __restrict__ a_dst1, int N) {
    extern __shared__ float smem[];
    float* Wsh = smem;                 // 8192 floats
    float* xs  = smem + F_IN * HDIM;   // 8192 floats
    int tid = threadIdx.x;
    int row0 = blockIdx.x * G1ROWS;
    if (row0 >= N) return;

    const float4* W4 = (const float4*)W1;
    float4* Wsh4 = (float4*)Wsh;
#pragma unroll
    for (int i = tid; i < F_IN * HDIM / 4; i += 256) Wsh4[i] = W4[i];

    int nrows = N - row0; if (nrows > G1ROWS) nrows = G1ROWS;
    const float4* x4 = (const float4*)(x + (size_t)row0 * F_IN);
    float4* xs4 = (float4*)xs;
    for (int i = tid; i < nrows * (F_IN / 4); i += 256) xs4[i] = x4[i];
    __syncthreads();

    int lane = tid & 31, warp = tid >> 5;
    int r0 = warp * 8;
    const unsigned long long* Wsh8 = (const unsigned long long*)Wsh;

    unsigned long long acc[8];
#pragma unroll
    for (int r = 0; r < 8; r++) acc[r] = 0ull;

    for (int k0 = 0; k0 < F_IN; k0 += 4) {
        float4 xv[8];
#pragma unroll
        for (int r = 0; r < 8; r++)
            xv[r] = *(const float4*)&xs[(r0 + r) * F_IN + k0];
#pragma unroll
        for (int kk = 0; kk < 4; kk++) {
            unsigned long long wp = Wsh8[(k0 + kk) * 32 + lane];
#pragma unroll
            for (int r = 0; r < 8; r++) {
                float xk = (kk == 0) ? xv[r].x : (kk == 1) ? xv[r].y
                          : (kk == 2) ? xv[r].z : xv[r].w;
                acc[r] = f32x2_fma(f32x2_bcast(xk), wp, acc[r]);
            }
        }
    }

    float2 asv = ((const float2*)a_src1)[lane];
    float2 adv = ((const float2*)a_dst1)[lane];
#pragma unroll
    for (int r = 0; r < 8; r++) {
        int lr = r0 + r;
        if (lr >= nrows) break;
        int row = row0 + lr;
        float c0 = __uint_as_float((unsigned int)acc[r]);
        float c1 = __uint_as_float((unsigned int)(acc[r] >> 32));
        g_h1h[(size_t)row * 32 + lane] = __floats2half2_rn(c0, c1);
        float aps = c0 * asv.x + c1 * asv.y;
        float apd = c0 * adv.x + c1 * adv.y;
#pragma unroll
        for (int o = 16; o; o >>= 1) {
            aps += __shfl_xor_sync(0xffffffffu, aps, o);
            apd += __shfl_xor_sync(0xffffffffu, apd, o);
        }
        if (lane == 0) { g_as1[row] = aps; g_ad1[row] = apd; }
    }
}

// ---------------- layer 1 aggregation + relu + layer 2 GEMM + alpha2 ----------------
__global__ __launch_bounds__(256) void agg1_k(
    const float* __restrict__ b1, const float* __restrict__ W2,
    const float* __restrict__ a_src2, const float* __restrict__ a_dst2, int N) {
    int gw = (int)((blockIdx.x * blockDim.x + threadIdx.x) >> 5);
    int lane = threadIdx.x & 31;
    if (gw >= N) return;
    int d = gw;
    int beg = g_rowptr[d], end = g_rowptr[d + 1];
    float ad = g_ad1[d];
    float accx = 0.f, accy = 0.f, denl = 0.f;
    for (int base = beg; base < end; base += 32) {
        int m = end - base; if (m > 32) m = 32;
        int s_l = 0; float p_l = 0.f;
        if (lane < m) {
            s_l = g_colsrc[base + lane];
            float ev = g_as1[s_l] + ad;
            ev = ev > 0.f ? ev : NEG_SLOPE * ev;
            p_l = __expf(ev);
        }
        denl += p_l;
#pragma unroll 8
        for (int j = 0; j < m; j++) {
            int s  = __shfl_sync(0xffffffffu, s_l, j);
            float p = __shfl_sync(0xffffffffu, p_l, j);
            __half2 hv = g_h1h[(size_t)s * 32 + lane];
            float2 f = __half22float2(hv);
            accx = fmaf(p, f.x, accx);
            accy = fmaf(p, f.y, accy);
        }
    }
    float den = denl;
#pragma unroll
    for (int o = 16; o; o >>= 1) den += __shfl_xor_sync(0xffffffffu, den, o);
    float inv = 1.0f / (den + 1e-16f);
    float2 bv = ((const float2*)b1)[lane];
    float h0 = accx * inv + bv.x; h0 = h0 > 0.f ? h0 : 0.f;
    float h1 = accy * inv + bv.y; h1 = h1 > 0.f ? h1 : 0.f;
    float4 w4 = ((const float4*)W2)[lane];
    float c0 = h0 * w4.x + h1 * w4.z;
    float c1 = h0 * w4.y + h1 * w4.w;
#pragma unroll
    for (int o = 16; o; o >>= 1) {
        c0 += __shfl_xor_sync(0xffffffffu, c0, o);
        c1 += __shfl_xor_sync(0xffffffffu, c1, o);
    }
    if (lane == 0) {
        g_pack2[d] = make_float4(c0, c1,
                                 c0 * a_src2[0] + c1 * a_src2[1],
                                 c0 * a_dst2[0] + c1 * a_dst2[1]);
    }
}

// ---------------- layer 2 aggregation ----------------
__global__ __launch_bounds__(256) void agg2_k(const float* __restrict__ b2,
                                              float* __restrict__ out, int N) {
    int gw = (int)((blockIdx.x * blockDim.x + threadIdx.x) >> 5);
    int lane = threadIdx.x & 31;
    if (gw >= N) return;
    int d = gw;
    int beg = g_rowptr[d], end = g_rowptr[d + 1];
    float ad = g_pack2[d].w;
    float a0 = 0.f, a1 = 0.f, den = 0.f;
    for (int e = beg + lane; e < end; e += 32) {
        int s = g_colsrc[e];
        float4 pv = g_pack2[s];
        float ev = pv.z + ad;
        ev = ev > 0.f ? ev : NEG_SLOPE * ev;
        float p = __expf(ev);
        a0 = fmaf(p, pv.x, a0);
        a1 = fmaf(p, pv.y, a1);
        den += p;
    }
#pragma unroll
    for (int o = 16; o; o >>= 1) {
        a0 += __shfl_xor_sync(0xffffffffu, a0, o);
        a1 += __shfl_xor_sync(0xffffffffu, a1, o);
        den += __shfl_xor_sync(0xffffffffu, den, o);
    }
    if (lane == 0) {
        float inv = 1.0f / (den + 1e-16f);
        ((float2*)out)[d] = make_float2(a0 * inv + b2[0], a1 * inv + b2[1]);
    }
}

// ---------------- launch ----------------
extern "C" void kernel_launch(void* const* d_in, const int* in_sizes, int n_in,
                              void* d_out, int out_size) {
    const float* x        = (const float*)d_in[0];
    const int*   ei       = (const int*)d_in[1];   // int32 (proven R1 trap / R4 probe)
    const float* W1       = (const float*)d_in[2];
    const float* a_src1   = (const float*)d_in[3];
    const float* a_dst1   = (const float*)d_in[4];
    const float* b1       = (const float*)d_in[5];
    const float* W2       = (const float*)d_in[6];
    const float* a_src2   = (const float*)d_in[7];
    const float* a_dst2   = (const float*)d_in[8];
    const float* b2       = (const float*)d_in[9];

    int N = in_sizes[0] / F_IN;
    int E = in_sizes[1] / 2;

    size_t g1smem = 2 * F_IN * HDIM * sizeof(float);  // 64KB

    static int inited = 0;
    static int have_stream = 0;
    static cudaStream_t s2;
    static cudaEvent_t evFork, evJoin;
    if (!inited) {
        cudaFuncSetAttribute(gemm1_k, cudaFuncAttributeMaxDynamicSharedMemorySize,
                             (int)g1smem);
        if (cudaStreamCreateWithFlags(&s2, cudaStreamNonBlocking) == cudaSuccess &&
            cudaEventCreateWithFlags(&evFork, cudaEventDisableTiming) == cudaSuccess &&
            cudaEventCreateWithFlags(&evJoin, cudaEventDisableTiming) == cudaSuccess) {
            have_stream = 1;
        }
        inited = 1;
    }

    int g1grid = (N + G1ROWS - 1) / G1ROWS;
    int nb = (N + 2047) / 2048;   // 49 for N=100k (<= 64)

    if (have_stream) { cudaEventRecord(evFork, 0); cudaStreamWaitEvent(s2, evFork, 0); }

    // Submission order: ncu profiles OUR 4th submitted kernel (R4/R5/R9 evidence)
    // => gemm1 is submission #4 this round.
    hist_k<<<(E + 255) / 256, 256>>>(ei, E, N);                 // #1 (also zeroes g_bsum)
    scan_k<<<nb, 256>>>(N, nb);                                 // #2
    scatter_k<<<(E + N + 255) / 256, 256>>>(ei, E, N);          // #3
    if (have_stream) {
        gemm1_k<<<g1grid, 256, g1smem, s2>>>(x, W1, a_src1, a_dst1, N);  // #4 <- ncu
        cudaEventRecord(evJoin, s2);
        cudaStreamWaitEvent(0, evJoin, 0);
    } else {
        gemm1_k<<<g1grid, 256, g1smem>>>(x, W1, a_src1, a_dst1, N);
    }
    agg1_k<<<(N + 7) / 8, 256>>>(b1, W2, a_src2, a_dst2, N);    // #5
    agg2_k<<<(N + 7) / 8, 256>>>(b2, (float*)d_out, N);         // #6
}